// round 9
// baseline (speedup 1.0000x reference)
#include <cuda_runtime.h>
#include <cstdint>

#define SEQ_L  16384
#define DIM_I  2048
#define DIM_N  2048
#define CHUNK  128
#define NCHUNK (SEQ_L / CHUNK)

// Scratch (device globals — no allocation allowed in kernel_launch)
__device__ __align__(256) float g_B  [(size_t)SEQ_L  * DIM_N];
__device__ __align__(256) float g_H  [(size_t)SEQ_L  * DIM_N];
__device__ __align__(256) float g_E  [(size_t)NCHUNK * DIM_N];
__device__ __align__(256) float g_Cin[(size_t)NCHUNK * DIM_N];

__device__ __forceinline__ uint32_t f2tf32(float f) {
    uint32_t u;
    asm("cvt.rna.tf32.f32 %0, %1;" : "=r"(u) : "f"(f));
    return u;
}
__device__ __forceinline__ uint32_t smem_u32(const void* p) {
    uint32_t a;
    asm("{ .reg .u64 t; cvta.to.shared.u64 t, %1; cvt.u32.u64 %0, t; }"
        : "=r"(a) : "l"(p));
    return a;
}

// ---------------------------------------------------------------------------
// tf32 mma.sync GEMM (NT): C[M,Nn] = A[M,K]*B[Nn,K]^T, raw fp32 in/out.
// Fragments are cvt.rna'd to tf32 AFTER the LDS (bit-identical to pre-rounding).
// CTA 128x128, BK=32, 128 thr = 4 warps (2x2), warp tile 64x64,
// 3-stage cp.async pipeline, XOR swizzle, 2 CTAs/SM.
// MODE 0 (GEMM1): epilogue also computes per-chunk scan tails E (chunk==m-tile).
// MODE 1 (GEMM2): epilogue fuses + xs*d_skip.
// ---------------------------------------------------------------------------
template<int MODE>
__global__ void __launch_bounds__(128)
gemm_mma(const float* __restrict__ A, const float* __restrict__ Bm,
         float* __restrict__ C, const float* __restrict__ sx,
         const float* __restrict__ sd,
         const float* __restrict__ lam, float* __restrict__ E,
         int M, int Nn, int K)
{
    constexpr int BK = 32, STAGES = 3;
    extern __shared__ uint32_t smp[];   // per stage: A 4096 words, B 4096 words

    const int tid    = threadIdx.x;
    const int lane   = tid & 31;
    const int wid    = tid >> 5;
    const int warp_m = wid & 1;        // 0..1  (64 rows)
    const int warp_n = wid >> 1;       // 0..1  (64 cols)
    const int g      = lane >> 2;      // 0..7
    const int c      = lane & 3;       // 0..3

    const int m0 = blockIdx.y * 128;
    const int n0 = blockIdx.x * 128;

    // ---- cp.async fill: thread -> rows (tid>>3)+{0,16,...,112}, 16B unit tid&7
    const int frow = tid >> 3;         // 0..15
    const int fu   = tid & 7;
    const int r7   = frow & 7;
    const float* Ag = A  + (size_t)(m0 + frow) * K + fu * 4;
    const float* Bg = Bm + (size_t)(n0 + frow) * K + fu * 4;
    const size_t rstep = (size_t)16 * K;

    const uint32_t sbw = smem_u32(smp);
    uint32_t dsto[8];
    #pragma unroll
    for (int i = 0; i < 8; ++i)
        dsto[i] = (uint32_t)(frow + i * 16) * 128u + (uint32_t)((fu ^ r7) << 4);

#define ISSUE_STAGE(st, kt) do {                                              \
    const uint32_t _bse = sbw + (uint32_t)(st) * 32768u;                      \
    const float* _ppa = Ag + (size_t)(kt) * BK;                               \
    const float* _ppb = Bg + (size_t)(kt) * BK;                               \
    _Pragma("unroll")                                                         \
    for (int _i = 0; _i < 8; ++_i) {                                          \
        asm volatile("cp.async.cg.shared.global [%0], [%1], 16;"              \
            :: "r"(_bse + dsto[_i]), "l"(_ppa + _i * rstep) : "memory");      \
        asm volatile("cp.async.cg.shared.global [%0], [%1], 16;"              \
            :: "r"(_bse + 16384u + dsto[_i]), "l"(_ppb + _i * rstep) : "memory"); \
    }                                                                         \
    asm volatile("cp.async.commit_group;" ::: "memory");                      \
  } while (0)

    // ---- fragment smem word offsets (swizzle term reduces to u^g)
    uint32_t arow[4], brow[8];
    #pragma unroll
    for (int mt = 0; mt < 4; ++mt)
        arow[mt] = (uint32_t)(warp_m * 64 + mt * 16 + g) * 32u;
    #pragma unroll
    for (int nt = 0; nt < 8; ++nt)
        brow[nt] = (uint32_t)(warp_n * 64 + nt * 8 + g) * 32u;

    float acc[4][8][4];
    #pragma unroll
    for (int mt = 0; mt < 4; ++mt)
        #pragma unroll
        for (int nt = 0; nt < 8; ++nt)
            #pragma unroll
            for (int r = 0; r < 4; ++r) acc[mt][nt][r] = 0.f;

    const int KT = K / BK;   // 64

    ISSUE_STAGE(0, 0);
    ISSUE_STAGE(1, 1);

    uint32_t af[2][4][4], bf[2][8][2];

// Load fragments and round to tf32 (rna) — same rounding as a pre-pass.
#define LOAD_FRAGS(buf, kc, sA, sB) do {                                      \
    const uint32_t _x0 = (uint32_t)(((2 * (kc))     ^ g) * 4 + c);            \
    const uint32_t _x1 = (uint32_t)(((2 * (kc) + 1) ^ g) * 4 + c);            \
    _Pragma("unroll")                                                         \
    for (int _mt = 0; _mt < 4; ++_mt) {                                       \
        af[buf][_mt][0] = f2tf32(__uint_as_float((sA)[arow[_mt] + _x0]));     \
        af[buf][_mt][1] = f2tf32(__uint_as_float((sA)[arow[_mt] + 256 + _x0]));\
        af[buf][_mt][2] = f2tf32(__uint_as_float((sA)[arow[_mt] + _x1]));     \
        af[buf][_mt][3] = f2tf32(__uint_as_float((sA)[arow[_mt] + 256 + _x1]));\
    }                                                                         \
    _Pragma("unroll")                                                         \
    for (int _nt = 0; _nt < 8; ++_nt) {                                       \
        bf[buf][_nt][0] = f2tf32(__uint_as_float((sB)[brow[_nt] + _x0]));     \
        bf[buf][_nt][1] = f2tf32(__uint_as_float((sB)[brow[_nt] + _x1]));     \
    }                                                                         \
  } while (0)

    for (int kt = 0; kt < KT; ++kt) {
        asm volatile("cp.async.wait_group 1;" ::: "memory");
        __syncthreads();
        if (kt + 2 < KT) ISSUE_STAGE((kt + 2) % STAGES, kt + 2);

        const uint32_t* sA = smp + (kt % STAGES) * 8192;
        const uint32_t* sB = sA + 4096;

        LOAD_FRAGS(0, 0, sA, sB);

        #pragma unroll
        for (int kc = 0; kc < 4; ++kc) {
            const int cur = kc & 1;
            const int nxt = cur ^ 1;
            if (kc < 3) LOAD_FRAGS(nxt, kc + 1, sA, sB);
            #pragma unroll
            for (int mt = 0; mt < 4; ++mt)
                #pragma unroll
                for (int nt = 0; nt < 8; ++nt) {
                    asm volatile(
                        "mma.sync.aligned.m16n8k8.row.col.f32.tf32.tf32.f32 "
                        "{%0,%1,%2,%3}, {%4,%5,%6,%7}, {%8,%9}, {%0,%1,%2,%3};"
                        : "+f"(acc[mt][nt][0]), "+f"(acc[mt][nt][1]),
                          "+f"(acc[mt][nt][2]), "+f"(acc[mt][nt][3])
                        : "r"(af[cur][mt][0]), "r"(af[cur][mt][1]),
                          "r"(af[cur][mt][2]), "r"(af[cur][mt][3]),
                          "r"(bf[cur][nt][0]), "r"(bf[cur][nt][1]));
                }
        }
    }
#undef ISSUE_STAGE
#undef LOAD_FRAGS

    // ---- epilogue: write C; c0:(g,2c) c1:(g,2c+1) c2:(g+8,2c) c3:(g+8,2c+1)
    #pragma unroll
    for (int mt = 0; mt < 4; ++mt) {
        const int r0 = m0 + warp_m * 64 + mt * 16 + g;
        const int r1 = r0 + 8;
        float* p0 = C + (size_t)r0 * Nn;
        float* p1 = C + (size_t)r1 * Nn;
        #pragma unroll
        for (int nt = 0; nt < 8; ++nt) {
            const int col = n0 + warp_n * 64 + nt * 8 + c * 2;
            float2 v0 = make_float2(acc[mt][nt][0], acc[mt][nt][1]);
            float2 v1 = make_float2(acc[mt][nt][2], acc[mt][nt][3]);
            if (MODE == 1) {
                const float2 x0 = *(const float2*)(sx + (size_t)r0 * Nn + col);
                const float2 x1 = *(const float2*)(sx + (size_t)r1 * Nn + col);
                const float2 dd = *(const float2*)(sd + col);
                v0.x = fmaf(x0.x, dd.x, v0.x);
                v0.y = fmaf(x0.y, dd.y, v0.y);
                v1.x = fmaf(x1.x, dd.x, v1.x);
                v1.y = fmaf(x1.y, dd.y, v1.y);
            }
            *(float2*)(p0 + col) = v0;
            *(float2*)(p1 + col) = v1;
        }
    }

    if (MODE == 0) {
        // ---- fused scan_chunk_reduce: this m-tile IS scan chunk m0/128.
        // Stash acc tile to smem (stride 132 to dodge bank conflicts), then
        // each thread serially scans one column.
        __syncthreads();   // pipeline smem no longer in use
        float* st = (float*)smp;
        #pragma unroll
        for (int mt = 0; mt < 4; ++mt) {
            const int lr0 = warp_m * 64 + mt * 16 + g;
            #pragma unroll
            for (int nt = 0; nt < 8; ++nt) {
                const int lc = warp_n * 64 + nt * 8 + c * 2;
                *(float2*)&st[(size_t)lr0 * 132 + lc] =
                    make_float2(acc[mt][nt][0], acc[mt][nt][1]);
                *(float2*)&st[(size_t)(lr0 + 8) * 132 + lc] =
                    make_float2(acc[mt][nt][2], acc[mt][nt][3]);
            }
        }
        __syncthreads();
        const float l = lam[n0 + tid];
        float h = 0.f;
        #pragma unroll 16
        for (int t = 0; t < 128; ++t)
            h = fmaf(l, h, st[(size_t)t * 132 + tid]);
        E[(size_t)(m0 >> 7) * DIM_N + n0 + tid] = h;
    }
}

// ---------------------------------------------------------------------------
// Scan combine: per-state carries across chunks, then apply.
// ---------------------------------------------------------------------------
__global__ void scan_carry(const float* __restrict__ lam,
                           const float* __restrict__ E,
                           float* __restrict__ Cin)
{
    const int n = blockIdx.x * blockDim.x + threadIdx.x;
    const float l = lam[n];
    float lT = l;
    #pragma unroll
    for (int i = 0; i < 7; ++i) lT *= lT;   // l^128
    float cin = 0.f;
    for (int cc = 0; cc < NCHUNK; cc += 8) {
        float e[8];
        #pragma unroll
        for (int i = 0; i < 8; ++i)
            e[i] = E[(size_t)(cc + i) * DIM_N + n];
        #pragma unroll
        for (int i = 0; i < 8; ++i) {
            Cin[(size_t)(cc + i) * DIM_N + n] = cin;
            cin = fmaf(lT, cin, e[i]);
        }
    }
}

__global__ void scan_apply(const float* __restrict__ Bmat,
                           const float* __restrict__ lam,
                           const float* __restrict__ Cin,
                           float* __restrict__ H)
{
    const int n = blockIdx.x * blockDim.x + threadIdx.x;
    const int cc = blockIdx.y;
    const float l = lam[n];
    const float* p = Bmat + (size_t)cc * CHUNK * DIM_N + n;
    float*       q = H    + (size_t)cc * CHUNK * DIM_N + n;
    float h = Cin[(size_t)cc * DIM_N + n];
    #pragma unroll 16
    for (int t = 0; t < CHUNK; ++t) {
        h = fmaf(l, h, p[(size_t)t * DIM_N]);
        q[(size_t)t * DIM_N] = h;
    }
}

// ---------------------------------------------------------------------------
extern "C" void kernel_launch(void* const* d_in, const int* in_sizes, int n_in,
                              void* d_out, int out_size)
{
    const float* xs     = (const float*)d_in[0];   // [SEQ_L, DIM_I]
    const float* lam    = (const float*)d_in[1];   // [DIM_N]
    const float* w_in   = (const float*)d_in[2];   // [DIM_N, DIM_I]
    const float* c_out  = (const float*)d_in[3];   // [DIM_I, DIM_N]
    const float* d_skip = (const float*)d_in[4];   // [DIM_I]
    float* out = (float*)d_out;                    // [SEQ_L, DIM_I]

    float *Bp, *Hp, *Ep, *Cp;
    cudaGetSymbolAddress((void**)&Bp, g_B);
    cudaGetSymbolAddress((void**)&Hp, g_H);
    cudaGetSymbolAddress((void**)&Ep, g_E);
    cudaGetSymbolAddress((void**)&Cp, g_Cin);

    const int SMEM_DYN = 3 * 32768;   // 96 KB
    cudaFuncSetAttribute(gemm_mma<0>,
        cudaFuncAttributeMaxDynamicSharedMemorySize, SMEM_DYN);
    cudaFuncSetAttribute(gemm_mma<1>,
        cudaFuncAttributeMaxDynamicSharedMemorySize, SMEM_DYN);

    // GEMM1: B = xs @ w_in^T  (+ fused per-chunk scan tails E)
    dim3 g1(DIM_N / 128, SEQ_L / 128);
    gemm_mma<0><<<g1, 128, SMEM_DYN>>>(xs, w_in, Bp, nullptr, nullptr,
                                       lam, Ep, SEQ_L, DIM_N, DIM_I);

    // Scan: carries, then apply
    scan_carry<<<DIM_N / 256, 256>>>(lam, Ep, Cp);
    dim3 gs(DIM_N / 256, NCHUNK);
    scan_apply<<<gs, 256>>>(Bp, lam, Cp, Hp);

    // GEMM2: out = H @ c_out^T + xs * d_skip
    dim3 g2(DIM_I / 128, SEQ_L / 128);
    gemm_mma<1><<<g2, 128, SMEM_DYN>>>(Hp, c_out, out, xs, d_skip,
                                       nullptr, nullptr, SEQ_L, DIM_I, DIM_N);
}

// round 10
// speedup vs baseline: 1.0899x; 1.0899x over previous
#include <cuda_runtime.h>
#include <cstdint>

#define SEQ_L  16384
#define DIM_I  2048
#define DIM_N  2048
#define CHUNK  128
#define NCHUNK (SEQ_L / CHUNK)

// Scratch (device globals — no allocation allowed in kernel_launch)
__device__ __align__(256) float g_B  [(size_t)SEQ_L  * DIM_N];
__device__ __align__(256) float g_H  [(size_t)SEQ_L  * DIM_N];
__device__ __align__(256) float g_E  [(size_t)NCHUNK * DIM_N];
__device__ __align__(256) float g_Cin[(size_t)NCHUNK * DIM_N];
__device__ __align__(256) float g_Xc [(size_t)SEQ_L  * DIM_I];
__device__ __align__(256) float g_Wc [(size_t)DIM_N  * DIM_I];
__device__ __align__(256) float g_Cc [(size_t)DIM_I  * DIM_N];

__device__ __forceinline__ uint32_t f2tf32(float f) {
    uint32_t u;
    asm("cvt.rna.tf32.f32 %0, %1;" : "=r"(u) : "f"(f));
    return u;
}
__device__ __forceinline__ uint32_t smem_u32(const void* p) {
    uint32_t a;
    asm("{ .reg .u64 t; cvta.to.shared.u64 t, %1; cvt.u32.u64 %0, t; }"
        : "=r"(a) : "l"(p));
    return a;
}

// ---------------------------------------------------------------------------
// One-time tf32 rounding of GEMM operands
// ---------------------------------------------------------------------------
__global__ void cvt_tf32_kernel(const float4* __restrict__ in,
                                float4* __restrict__ out, int n4)
{
    int i = blockIdx.x * blockDim.x + threadIdx.x;
    if (i < n4) {
        float4 v = in[i];
        float4 o;
        o.x = __uint_as_float(f2tf32(v.x));
        o.y = __uint_as_float(f2tf32(v.y));
        o.z = __uint_as_float(f2tf32(v.z));
        o.w = __uint_as_float(f2tf32(v.w));
        out[i] = o;
    }
}

// ---------------------------------------------------------------------------
// tf32 mma.sync GEMM (NT): C[M,Nn] = A[M,K]*B[Nn,K]^T. A,B pre-rounded tf32.
// CTA 128x128, BK=32, 128 thr = 4 warps (2x2), warp tile 64x64,
// 3-stage cp.async pipeline, XOR swizzle, 2 CTAs/SM.  (round-8 hot loop,
// byte-identical — measured 69.2% tensor.)
// MODE 0 (GEMM1): epilogue also computes per-chunk scan tails E (chunk==m-tile).
// MODE 1 (GEMM2): epilogue fuses + xs*d_skip.
// ---------------------------------------------------------------------------
template<int MODE>
__global__ void __launch_bounds__(128)
gemm_mma(const float* __restrict__ A, const float* __restrict__ Bm,
         float* __restrict__ C, const float* __restrict__ sx,
         const float* __restrict__ sd,
         const float* __restrict__ lam, float* __restrict__ E,
         int M, int Nn, int K)
{
    constexpr int BK = 32, STAGES = 3;
    extern __shared__ uint32_t smp[];   // per stage: A 4096 words, B 4096 words

    const int tid    = threadIdx.x;
    const int lane   = tid & 31;
    const int wid    = tid >> 5;
    const int warp_m = wid & 1;        // 0..1  (64 rows)
    const int warp_n = wid >> 1;       // 0..1  (64 cols)
    const int g      = lane >> 2;      // 0..7
    const int c      = lane & 3;       // 0..3

    const int m0 = blockIdx.y * 128;
    const int n0 = blockIdx.x * 128;

    // ---- cp.async fill: thread -> rows (tid>>3)+{0,16,...,112}, 16B unit tid&7
    const int frow = tid >> 3;         // 0..15
    const int fu   = tid & 7;
    const int r7   = frow & 7;
    const float* Ag = A  + (size_t)(m0 + frow) * K + fu * 4;
    const float* Bg = Bm + (size_t)(n0 + frow) * K + fu * 4;
    const size_t rstep = (size_t)16 * K;

    const uint32_t sbw = smem_u32(smp);
    uint32_t dsto[8];
    #pragma unroll
    for (int i = 0; i < 8; ++i)
        dsto[i] = (uint32_t)(frow + i * 16) * 128u + (uint32_t)((fu ^ r7) << 4);

#define ISSUE_STAGE(st, kt) do {                                              \
    const uint32_t _bse = sbw + (uint32_t)(st) * 32768u;                      \
    const float* _ppa = Ag + (size_t)(kt) * BK;                               \
    const float* _ppb = Bg + (size_t)(kt) * BK;                               \
    _Pragma("unroll")                                                         \
    for (int _i = 0; _i < 8; ++_i) {                                          \
        asm volatile("cp.async.cg.shared.global [%0], [%1], 16;"              \
            :: "r"(_bse + dsto[_i]), "l"(_ppa + _i * rstep) : "memory");      \
        asm volatile("cp.async.cg.shared.global [%0], [%1], 16;"              \
            :: "r"(_bse + 16384u + dsto[_i]), "l"(_ppb + _i * rstep) : "memory"); \
    }                                                                         \
    asm volatile("cp.async.commit_group;" ::: "memory");                      \
  } while (0)

    // ---- fragment smem word offsets (swizzle term reduces to u^g)
    uint32_t arow[4], brow[8];
    #pragma unroll
    for (int mt = 0; mt < 4; ++mt)
        arow[mt] = (uint32_t)(warp_m * 64 + mt * 16 + g) * 32u;
    #pragma unroll
    for (int nt = 0; nt < 8; ++nt)
        brow[nt] = (uint32_t)(warp_n * 64 + nt * 8 + g) * 32u;

    float acc[4][8][4];
    #pragma unroll
    for (int mt = 0; mt < 4; ++mt)
        #pragma unroll
        for (int nt = 0; nt < 8; ++nt)
            #pragma unroll
            for (int r = 0; r < 4; ++r) acc[mt][nt][r] = 0.f;

    const int KT = K / BK;   // 64

    ISSUE_STAGE(0, 0);
    ISSUE_STAGE(1, 1);

    uint32_t af[2][4][4], bf[2][8][2];

#define LOAD_FRAGS(buf, kc, sA, sB) do {                                      \
    const uint32_t _x0 = (uint32_t)(((2 * (kc))     ^ g) * 4 + c);            \
    const uint32_t _x1 = (uint32_t)(((2 * (kc) + 1) ^ g) * 4 + c);            \
    _Pragma("unroll")                                                         \
    for (int _mt = 0; _mt < 4; ++_mt) {                                       \
        af[buf][_mt][0] = (sA)[arow[_mt] + _x0];                              \
        af[buf][_mt][1] = (sA)[arow[_mt] + 256 + _x0];                        \
        af[buf][_mt][2] = (sA)[arow[_mt] + _x1];                              \
        af[buf][_mt][3] = (sA)[arow[_mt] + 256 + _x1];                        \
    }                                                                         \
    _Pragma("unroll")                                                         \
    for (int _nt = 0; _nt < 8; ++_nt) {                                       \
        bf[buf][_nt][0] = (sB)[brow[_nt] + _x0];                              \
        bf[buf][_nt][1] = (sB)[brow[_nt] + _x1];                              \
    }                                                                         \
  } while (0)

    for (int kt = 0; kt < KT; ++kt) {
        asm volatile("cp.async.wait_group 1;" ::: "memory");
        __syncthreads();
        if (kt + 2 < KT) ISSUE_STAGE((kt + 2) % STAGES, kt + 2);

        const uint32_t* sA = smp + (kt % STAGES) * 8192;
        const uint32_t* sB = sA + 4096;

        LOAD_FRAGS(0, 0, sA, sB);

        #pragma unroll
        for (int kc = 0; kc < 4; ++kc) {
            const int cur = kc & 1;
            const int nxt = cur ^ 1;
            if (kc < 3) LOAD_FRAGS(nxt, kc + 1, sA, sB);
            #pragma unroll
            for (int mt = 0; mt < 4; ++mt)
                #pragma unroll
                for (int nt = 0; nt < 8; ++nt) {
                    asm volatile(
                        "mma.sync.aligned.m16n8k8.row.col.f32.tf32.tf32.f32 "
                        "{%0,%1,%2,%3}, {%4,%5,%6,%7}, {%8,%9}, {%0,%1,%2,%3};"
                        : "+f"(acc[mt][nt][0]), "+f"(acc[mt][nt][1]),
                          "+f"(acc[mt][nt][2]), "+f"(acc[mt][nt][3])
                        : "r"(af[cur][mt][0]), "r"(af[cur][mt][1]),
                          "r"(af[cur][mt][2]), "r"(af[cur][mt][3]),
                          "r"(bf[cur][nt][0]), "r"(bf[cur][nt][1]));
                }
        }
    }
#undef ISSUE_STAGE
#undef LOAD_FRAGS

    // ---- epilogue: write C; c0:(g,2c) c1:(g,2c+1) c2:(g+8,2c) c3:(g+8,2c+1)
    #pragma unroll
    for (int mt = 0; mt < 4; ++mt) {
        const int r0 = m0 + warp_m * 64 + mt * 16 + g;
        const int r1 = r0 + 8;
        float* p0 = C + (size_t)r0 * Nn;
        float* p1 = C + (size_t)r1 * Nn;
        #pragma unroll
        for (int nt = 0; nt < 8; ++nt) {
            const int col = n0 + warp_n * 64 + nt * 8 + c * 2;
            float2 v0 = make_float2(acc[mt][nt][0], acc[mt][nt][1]);
            float2 v1 = make_float2(acc[mt][nt][2], acc[mt][nt][3]);
            if (MODE == 1) {
                const float2 x0 = *(const float2*)(sx + (size_t)r0 * Nn + col);
                const float2 x1 = *(const float2*)(sx + (size_t)r1 * Nn + col);
                const float2 dd = *(const float2*)(sd + col);
                v0.x = fmaf(x0.x, dd.x, v0.x);
                v0.y = fmaf(x0.y, dd.y, v0.y);
                v1.x = fmaf(x1.x, dd.x, v1.x);
                v1.y = fmaf(x1.y, dd.y, v1.y);
            }
            *(float2*)(p0 + col) = v0;
            *(float2*)(p1 + col) = v1;
        }
    }

    if (MODE == 0) {
        // ---- fused scan_chunk_reduce: this m-tile IS scan chunk m0/128.
        // Stash acc tile to (now idle) pipeline smem with stride 132, then
        // each of the 128 threads serially scans its own state column.
        __syncthreads();
        float* st = (float*)smp;
        #pragma unroll
        for (int mt = 0; mt < 4; ++mt) {
            const int lr0 = warp_m * 64 + mt * 16 + g;
            #pragma unroll
            for (int nt = 0; nt < 8; ++nt) {
                const int lc = warp_n * 64 + nt * 8 + c * 2;
                *(float2*)&st[(size_t)lr0 * 132 + lc] =
                    make_float2(acc[mt][nt][0], acc[mt][nt][1]);
                *(float2*)&st[(size_t)(lr0 + 8) * 132 + lc] =
                    make_float2(acc[mt][nt][2], acc[mt][nt][3]);
            }
        }
        __syncthreads();
        const float l = lam[n0 + tid];
        float h = 0.f;
        #pragma unroll 16
        for (int t = 0; t < 128; ++t)
            h = fmaf(l, h, st[(size_t)t * 132 + tid]);
        E[(size_t)(m0 >> 7) * DIM_N + n0 + tid] = h;
    }
}

// ---------------------------------------------------------------------------
// Scan combine: per-state carries across chunks, then apply.
// ---------------------------------------------------------------------------
__global__ void scan_carry(const float* __restrict__ lam,
                           const float* __restrict__ E,
                           float* __restrict__ Cin)
{
    const int n = blockIdx.x * blockDim.x + threadIdx.x;
    const float l = lam[n];
    float lT = l;
    #pragma unroll
    for (int i = 0; i < 7; ++i) lT *= lT;   // l^128
    float cin = 0.f;
    for (int cc = 0; cc < NCHUNK; cc += 8) {
        float e[8];
        #pragma unroll
        for (int i = 0; i < 8; ++i)
            e[i] = E[(size_t)(cc + i) * DIM_N + n];
        #pragma unroll
        for (int i = 0; i < 8; ++i) {
            Cin[(size_t)(cc + i) * DIM_N + n] = cin;
            cin = fmaf(lT, cin, e[i]);
        }
    }
}

// writes tf32-rounded H (consumed only as GEMM2's A operand)
__global__ void scan_apply(const float* __restrict__ Bmat,
                           const float* __restrict__ lam,
                           const float* __restrict__ Cin,
                           float* __restrict__ H)
{
    const int n = blockIdx.x * blockDim.x + threadIdx.x;
    const int cc = blockIdx.y;
    const float l = lam[n];
    const float* p = Bmat + (size_t)cc * CHUNK * DIM_N + n;
    float*       q = H    + (size_t)cc * CHUNK * DIM_N + n;
    float h = Cin[(size_t)cc * DIM_N + n];
    #pragma unroll 16
    for (int t = 0; t < CHUNK; ++t) {
        h = fmaf(l, h, p[(size_t)t * DIM_N]);
        q[(size_t)t * DIM_N] = __uint_as_float(f2tf32(h));
    }
}

// ---------------------------------------------------------------------------
extern "C" void kernel_launch(void* const* d_in, const int* in_sizes, int n_in,
                              void* d_out, int out_size)
{
    const float* xs     = (const float*)d_in[0];   // [SEQ_L, DIM_I]
    const float* lam    = (const float*)d_in[1];   // [DIM_N]
    const float* w_in   = (const float*)d_in[2];   // [DIM_N, DIM_I]
    const float* c_out  = (const float*)d_in[3];   // [DIM_I, DIM_N]
    const float* d_skip = (const float*)d_in[4];   // [DIM_I]
    float* out = (float*)d_out;                    // [SEQ_L, DIM_I]

    float *Bp, *Hp, *Ep, *Cp, *Xc, *Wc, *Cc;
    cudaGetSymbolAddress((void**)&Bp, g_B);
    cudaGetSymbolAddress((void**)&Hp, g_H);
    cudaGetSymbolAddress((void**)&Ep, g_E);
    cudaGetSymbolAddress((void**)&Cp, g_Cin);
    cudaGetSymbolAddress((void**)&Xc, g_Xc);
    cudaGetSymbolAddress((void**)&Wc, g_Wc);
    cudaGetSymbolAddress((void**)&Cc, g_Cc);

    const int SMEM_DYN = 3 * 32768;   // 96 KB
    cudaFuncSetAttribute(gemm_mma<0>,
        cudaFuncAttributeMaxDynamicSharedMemorySize, SMEM_DYN);
    cudaFuncSetAttribute(gemm_mma<1>,
        cudaFuncAttributeMaxDynamicSharedMemorySize, SMEM_DYN);

    // Pre-round operands to tf32
    {
        int n4 = SEQ_L * DIM_I / 4;
        cvt_tf32_kernel<<<n4 / 256, 256>>>((const float4*)xs, (float4*)Xc, n4);
        n4 = DIM_N * DIM_I / 4;
        cvt_tf32_kernel<<<n4 / 256, 256>>>((const float4*)w_in, (float4*)Wc, n4);
        n4 = DIM_I * DIM_N / 4;
        cvt_tf32_kernel<<<n4 / 256, 256>>>((const float4*)c_out, (float4*)Cc, n4);
    }

    // GEMM1: B = xs @ w_in^T  (+ fused per-chunk scan tails E)
    dim3 g1(DIM_N / 128, SEQ_L / 128);
    gemm_mma<0><<<g1, 128, SMEM_DYN>>>(Xc, Wc, Bp, nullptr, nullptr,
                                       lam, Ep, SEQ_L, DIM_N, DIM_I);

    // Scan: carries across chunks, then apply (writes tf32-rounded H)
    scan_carry<<<DIM_N / 256, 256>>>(lam, Ep, Cp);
    dim3 gs(DIM_N / 256, NCHUNK);
    scan_apply<<<gs, 256>>>(Bp, lam, Cp, Hp);

    // GEMM2: out = H @ c_out^T + xs * d_skip
    dim3 g2(DIM_I / 128, SEQ_L / 128);
    gemm_mma<1><<<g2, 128, SMEM_DYN>>>(Hp, Cc, out, xs, d_skip,
                                       nullptr, nullptr, SEQ_L, DIM_I, DIM_N);
}

// round 12
// speedup vs baseline: 1.0914x; 1.0014x over previous
#include <cuda_runtime.h>
#include <cstdint>

#define SEQ_L  16384
#define DIM_I  2048
#define DIM_N  2048
#define CHUNK  128
#define NCHUNK (SEQ_L / CHUNK)
#define GRID_P 296

// Scratch (device globals — no allocation allowed in kernel_launch)
__device__ __align__(256) float g_B  [(size_t)SEQ_L  * DIM_N];
__device__ __align__(256) float g_H  [(size_t)SEQ_L  * DIM_N];
__device__ __align__(256) float g_E  [(size_t)NCHUNK * DIM_N];
__device__ __align__(256) float g_Cin[(size_t)NCHUNK * DIM_N];
__device__ __align__(256) float g_Xc [(size_t)SEQ_L  * DIM_I];
__device__ __align__(256) float g_Wc [(size_t)DIM_N  * DIM_I];
__device__ __align__(256) float g_Cc [(size_t)DIM_I  * DIM_N];

__device__ __forceinline__ uint32_t f2tf32(float f) {
    uint32_t u;
    asm("cvt.rna.tf32.f32 %0, %1;" : "=r"(u) : "f"(f));
    return u;
}
__device__ __forceinline__ uint32_t smem_u32(const void* p) {
    uint32_t a;
    asm("{ .reg .u64 t; cvta.to.shared.u64 t, %1; cvt.u32.u64 %0, t; }"
        : "=r"(a) : "l"(p));
    return a;
}

// ---------------------------------------------------------------------------
// Shared GEMM inner-loop macros. Each kernel using them must declare locals:
//   uint32_t af[2][4][4], bf[2][8][2];  float acc[4][8][4];
//   uint32_t arow[4], brow[8];  int g, c;
// ---------------------------------------------------------------------------
#define LOAD_FRAGS(buf, kc, sA, sB) do {                                      \
    const uint32_t _x0 = (uint32_t)(((2 * (kc))     ^ g) * 4 + c);            \
    const uint32_t _x1 = (uint32_t)(((2 * (kc) + 1) ^ g) * 4 + c);            \
    _Pragma("unroll")                                                         \
    for (int _mt = 0; _mt < 4; ++_mt) {                                       \
        af[buf][_mt][0] = (sA)[arow[_mt] + _x0];                              \
        af[buf][_mt][1] = (sA)[arow[_mt] + 256 + _x0];                        \
        af[buf][_mt][2] = (sA)[arow[_mt] + _x1];                              \
        af[buf][_mt][3] = (sA)[arow[_mt] + 256 + _x1];                        \
    }                                                                         \
    _Pragma("unroll")                                                         \
    for (int _nt = 0; _nt < 8; ++_nt) {                                       \
        bf[buf][_nt][0] = (sB)[brow[_nt] + _x0];                              \
        bf[buf][_nt][1] = (sB)[brow[_nt] + _x1];                              \
    }                                                                         \
  } while (0)

#define MMA_KC(cur) do {                                                      \
    _Pragma("unroll")                                                         \
    for (int _mt = 0; _mt < 4; ++_mt)                                         \
        _Pragma("unroll")                                                     \
        for (int _nt = 0; _nt < 8; ++_nt) {                                   \
            asm volatile(                                                     \
                "mma.sync.aligned.m16n8k8.row.col.f32.tf32.tf32.f32 "         \
                "{%0,%1,%2,%3}, {%4,%5,%6,%7}, {%8,%9}, {%0,%1,%2,%3};"       \
                : "+f"(acc[_mt][_nt][0]), "+f"(acc[_mt][_nt][1]),             \
                  "+f"(acc[_mt][_nt][2]), "+f"(acc[_mt][_nt][3])              \
                : "r"(af[cur][_mt][0]), "r"(af[cur][_mt][1]),                 \
                  "r"(af[cur][_mt][2]), "r"(af[cur][_mt][3]),                 \
                  "r"(bf[cur][_nt][0]), "r"(bf[cur][_nt][1]));                \
        }                                                                     \
  } while (0)

// ---------------------------------------------------------------------------
// One-shot tf32 rounding of all three operands (grid-partitioned)
// ---------------------------------------------------------------------------
__global__ void cvt3_tf32_kernel(const float4* __restrict__ a, float4* __restrict__ oa, int na4,
                                 const float4* __restrict__ b, float4* __restrict__ ob, int nb4,
                                 const float4* __restrict__ cc, float4* __restrict__ oc, int nc4)
{
    int i = blockIdx.x * blockDim.x + threadIdx.x;
    const float4* in; float4* out; int idx;
    if (i < na4)            { in = a;  out = oa; idx = i; }
    else if (i < na4 + nb4) { in = b;  out = ob; idx = i - na4; }
    else if (i < na4 + nb4 + nc4) { in = cc; out = oc; idx = i - na4 - nb4; }
    else return;
    float4 v = in[idx];
    float4 o;
    o.x = __uint_as_float(f2tf32(v.x));
    o.y = __uint_as_float(f2tf32(v.y));
    o.z = __uint_as_float(f2tf32(v.z));
    o.w = __uint_as_float(f2tf32(v.w));
    out[idx] = o;
}

// ---------------------------------------------------------------------------
// GEMM1 (waved): B = A*Bm^T + fused per-chunk scan tails E.
// CTA 128x128, BK=32, 4 warps (2x2), warp tile 64x64, 3-stage cp.async,
// XOR swizzle, 2 CTAs/SM.  (round-10 kernel, measured 646us / 70% tensor)
// ---------------------------------------------------------------------------
__global__ void __launch_bounds__(128)
gemm_g1(const float* __restrict__ A, const float* __restrict__ Bm,
        float* __restrict__ C,
        const float* __restrict__ lam, float* __restrict__ E,
        int M, int Nn, int K)
{
    constexpr int BK = 32, STAGES = 3;
    extern __shared__ uint32_t smp[];

    const int tid    = threadIdx.x;
    const int lane   = tid & 31;
    const int wid    = tid >> 5;
    const int warp_m = wid & 1;
    const int warp_n = wid >> 1;
    const int g      = lane >> 2;
    const int c      = lane & 3;

    const int m0 = blockIdx.y * 128;
    const int n0 = blockIdx.x * 128;

    const int frow = tid >> 3;
    const int fu   = tid & 7;
    const int r7   = frow & 7;
    const float* Ag = A  + (size_t)(m0 + frow) * K + fu * 4;
    const float* Bg = Bm + (size_t)(n0 + frow) * K + fu * 4;
    const size_t rstep = (size_t)16 * K;

    const uint32_t sbw = smem_u32(smp);
    uint32_t dsto[8];
    #pragma unroll
    for (int i = 0; i < 8; ++i)
        dsto[i] = (uint32_t)(frow + i * 16) * 128u + (uint32_t)((fu ^ r7) << 4);

#define ISSUE_STAGE(st, kt) do {                                              \
    const uint32_t _bse = sbw + (uint32_t)(st) * 32768u;                      \
    const float* _ppa = Ag + (size_t)(kt) * BK;                               \
    const float* _ppb = Bg + (size_t)(kt) * BK;                               \
    _Pragma("unroll")                                                         \
    for (int _i = 0; _i < 8; ++_i) {                                          \
        asm volatile("cp.async.cg.shared.global [%0], [%1], 16;"              \
            :: "r"(_bse + dsto[_i]), "l"(_ppa + _i * rstep) : "memory");      \
        asm volatile("cp.async.cg.shared.global [%0], [%1], 16;"              \
            :: "r"(_bse + 16384u + dsto[_i]), "l"(_ppb + _i * rstep) : "memory"); \
    }                                                                         \
    asm volatile("cp.async.commit_group;" ::: "memory");                      \
  } while (0)

    uint32_t arow[4], brow[8];
    #pragma unroll
    for (int mt = 0; mt < 4; ++mt)
        arow[mt] = (uint32_t)(warp_m * 64 + mt * 16 + g) * 32u;
    #pragma unroll
    for (int nt = 0; nt < 8; ++nt)
        brow[nt] = (uint32_t)(warp_n * 64 + nt * 8 + g) * 32u;

    float acc[4][8][4];
    #pragma unroll
    for (int mt = 0; mt < 4; ++mt)
        #pragma unroll
        for (int nt = 0; nt < 8; ++nt)
            #pragma unroll
            for (int r = 0; r < 4; ++r) acc[mt][nt][r] = 0.f;

    const int KT = K / BK;

    ISSUE_STAGE(0, 0);
    ISSUE_STAGE(1, 1);

    uint32_t af[2][4][4], bf[2][8][2];

    for (int kt = 0; kt < KT; ++kt) {
        asm volatile("cp.async.wait_group 1;" ::: "memory");
        __syncthreads();
        if (kt + 2 < KT) ISSUE_STAGE((kt + 2) % STAGES, kt + 2);

        const uint32_t* sA = smp + (kt % STAGES) * 8192;
        const uint32_t* sB = sA + 4096;

        LOAD_FRAGS(0, 0, sA, sB);
        #pragma unroll
        for (int kc = 0; kc < 4; ++kc) {
            const int cur = kc & 1;
            if (kc < 3) LOAD_FRAGS(cur ^ 1, kc + 1, sA, sB);
            MMA_KC(cur);
        }
    }
#undef ISSUE_STAGE

    // epilogue: write C
    #pragma unroll
    for (int mt = 0; mt < 4; ++mt) {
        const int r0 = m0 + warp_m * 64 + mt * 16 + g;
        const int r1 = r0 + 8;
        float* p0 = C + (size_t)r0 * Nn;
        float* p1 = C + (size_t)r1 * Nn;
        #pragma unroll
        for (int nt = 0; nt < 8; ++nt) {
            const int col = n0 + warp_n * 64 + nt * 8 + c * 2;
            *(float2*)(p0 + col) = make_float2(acc[mt][nt][0], acc[mt][nt][1]);
            *(float2*)(p1 + col) = make_float2(acc[mt][nt][2], acc[mt][nt][3]);
        }
    }

    // fused scan_chunk_reduce: this m-tile IS scan chunk m0/128
    __syncthreads();
    float* st = (float*)smp;
    #pragma unroll
    for (int mt = 0; mt < 4; ++mt) {
        const int lr0 = warp_m * 64 + mt * 16 + g;
        #pragma unroll
        for (int nt = 0; nt < 8; ++nt) {
            const int lc = warp_n * 64 + nt * 8 + c * 2;
            *(float2*)&st[(size_t)lr0 * 132 + lc] =
                make_float2(acc[mt][nt][0], acc[mt][nt][1]);
            *(float2*)&st[(size_t)(lr0 + 8) * 132 + lc] =
                make_float2(acc[mt][nt][2], acc[mt][nt][3]);
        }
    }
    __syncthreads();
    const float l = lam[n0 + tid];
    float h = 0.f;
    #pragma unroll 16
    for (int t = 0; t < 128; ++t)
        h = fmaf(l, h, st[(size_t)t * 132 + tid]);
    E[(size_t)(m0 >> 7) * DIM_N + n0 + tid] = h;
}

// ---------------------------------------------------------------------------
// GEMM2 (persistent): out = A*Bm^T + sx*sd. Same hot loop; grid 296 (2/SM),
// cp.async ring carried continuously across tiles (running stage counters).
// Epilogue is register/global-only so in-flight next-tile fills are safe.
// ---------------------------------------------------------------------------
__global__ void __launch_bounds__(128)
gemm_g2(const float* __restrict__ A, const float* __restrict__ Bm,
        float* __restrict__ C, const float* __restrict__ sx,
        const float* __restrict__ sd, int M, int Nn, int K)
{
    constexpr int BK = 32;
    extern __shared__ uint32_t smp[];

    const int tid    = threadIdx.x;
    const int lane   = tid & 31;
    const int wid    = tid >> 5;
    const int warp_m = wid & 1;
    const int warp_n = wid >> 1;
    const int g      = lane >> 2;
    const int c      = lane & 3;

    const int NBN    = Nn / 128;
    const int NTILES = (M / 128) * NBN;

    const int frow = tid >> 3;
    const int fu   = tid & 7;
    const int r7   = frow & 7;
    const size_t rstep = (size_t)16 * K;

    const uint32_t sbw = smem_u32(smp);
    uint32_t dsto[8];
    #pragma unroll
    for (int i = 0; i < 8; ++i)
        dsto[i] = (uint32_t)(frow + i * 16) * 128u + (uint32_t)((fu ^ r7) << 4);

#define ISSUE_PTR(pa_, pb_, st) do {                                          \
    const uint32_t _bse = sbw + (uint32_t)(st) * 32768u;                      \
    const float* _ppa = (pa_);                                                \
    const float* _ppb = (pb_);                                                \
    _Pragma("unroll")                                                         \
    for (int _i = 0; _i < 8; ++_i) {                                          \
        asm volatile("cp.async.cg.shared.global [%0], [%1], 16;"              \
            :: "r"(_bse + dsto[_i]), "l"(_ppa + _i * rstep) : "memory");      \
        asm volatile("cp.async.cg.shared.global [%0], [%1], 16;"              \
            :: "r"(_bse + 16384u + dsto[_i]), "l"(_ppb + _i * rstep) : "memory"); \
    }                                                                         \
    asm volatile("cp.async.commit_group;" ::: "memory");                      \
  } while (0)

    uint32_t arow[4], brow[8];
    #pragma unroll
    for (int mt = 0; mt < 4; ++mt)
        arow[mt] = (uint32_t)(warp_m * 64 + mt * 16 + g) * 32u;
    #pragma unroll
    for (int nt = 0; nt < 8; ++nt)
        brow[nt] = (uint32_t)(warp_n * 64 + nt * 8 + g) * 32u;

    float acc[4][8][4];
    #pragma unroll
    for (int mt = 0; mt < 4; ++mt)
        #pragma unroll
        for (int nt = 0; nt < 8; ++nt)
            #pragma unroll
            for (int r = 0; r < 4; ++r) acc[mt][nt][r] = 0.f;

    uint32_t af[2][4][4], bf[2][8][2];

    const int bid = blockIdx.x;
    const int cnt = (NTILES - bid + GRID_P - 1) / GRID_P;
    if (cnt <= 0) return;

    // prologue: first two stages of first tile
    {
        const int m0 = (bid / NBN) * 128, n0 = (bid % NBN) * 128;
        const float* pA = A  + (size_t)(m0 + frow) * K + fu * 4;
        const float* pB = Bm + (size_t)(n0 + frow) * K + fu * 4;
        ISSUE_PTR(pA, pB, 0);
        ISSUE_PTR(pA + BK, pB + BK, 1);
    }

    int st_cur = 0, st_nxt = 2;   // stage of iter q, and of iter q+2

    for (int j = 0; j < cnt; ++j) {
        const int tile = bid + j * GRID_P;
        const int m0 = (tile / NBN) * 128;
        const int n0 = (tile % NBN) * 128;
        const float* curA = A  + (size_t)(m0 + frow) * K + fu * 4;
        const float* curB = Bm + (size_t)(n0 + frow) * K + fu * 4;

        for (int kt = 0; kt < 64; ++kt) {
            asm volatile("cp.async.wait_group 1;" ::: "memory");
            __syncthreads();

            if (kt + 2 < 64) {
                ISSUE_PTR(curA + (size_t)(kt + 2) * BK,
                          curB + (size_t)(kt + 2) * BK, st_nxt);
            } else if (j + 1 < cnt) {
                const int t2 = tile + GRID_P;
                const int m2 = (t2 / NBN) * 128, n2 = (t2 % NBN) * 128;
                const float* nA = A  + (size_t)(m2 + frow) * K + fu * 4
                                     + (size_t)(kt + 2 - 64) * BK;
                const float* nB = Bm + (size_t)(n2 + frow) * K + fu * 4
                                     + (size_t)(kt + 2 - 64) * BK;
                ISSUE_PTR(nA, nB, st_nxt);
            } else {
                asm volatile("cp.async.commit_group;" ::: "memory");
            }

            const uint32_t* sA = smp + st_cur * 8192;
            const uint32_t* sB = sA + 4096;

            LOAD_FRAGS(0, 0, sA, sB);
            #pragma unroll
            for (int kc = 0; kc < 4; ++kc) {
                const int cur = kc & 1;
                if (kc < 3) LOAD_FRAGS(cur ^ 1, kc + 1, sA, sB);
                MMA_KC(cur);
            }

            st_cur = (st_cur == 2) ? 0 : st_cur + 1;
            st_nxt = (st_nxt == 2) ? 0 : st_nxt + 1;
        }

        // epilogue (registers + global only — smem stays owned by the ring)
        #pragma unroll
        for (int mt = 0; mt < 4; ++mt) {
            const int r0 = m0 + warp_m * 64 + mt * 16 + g;
            const int r1 = r0 + 8;
            float* p0 = C + (size_t)r0 * Nn;
            float* p1 = C + (size_t)r1 * Nn;
            #pragma unroll
            for (int nt = 0; nt < 8; ++nt) {
                const int col = n0 + warp_n * 64 + nt * 8 + c * 2;
                float2 v0 = make_float2(acc[mt][nt][0], acc[mt][nt][1]);
                float2 v1 = make_float2(acc[mt][nt][2], acc[mt][nt][3]);
                const float2 x0 = *(const float2*)(sx + (size_t)r0 * Nn + col);
                const float2 x1 = *(const float2*)(sx + (size_t)r1 * Nn + col);
                const float2 dd = *(const float2*)(sd + col);
                v0.x = fmaf(x0.x, dd.x, v0.x);
                v0.y = fmaf(x0.y, dd.y, v0.y);
                v1.x = fmaf(x1.x, dd.x, v1.x);
                v1.y = fmaf(x1.y, dd.y, v1.y);
                *(float2*)(p0 + col) = v0;
                *(float2*)(p1 + col) = v1;
                acc[mt][nt][0] = 0.f; acc[mt][nt][1] = 0.f;
                acc[mt][nt][2] = 0.f; acc[mt][nt][3] = 0.f;
            }
        }
    }
#undef ISSUE_PTR
}

// ---------------------------------------------------------------------------
// Scan combine: per-state carries across chunks, then apply (2 states/thread).
// ---------------------------------------------------------------------------
__global__ void scan_carry(const float* __restrict__ lam,
                           const float* __restrict__ E,
                           float* __restrict__ Cin)
{
    const int n = blockIdx.x * blockDim.x + threadIdx.x;
    const float l = lam[n];
    float lT = l;
    #pragma unroll
    for (int i = 0; i < 7; ++i) lT *= lT;   // l^128
    float cin = 0.f;
    for (int cc = 0; cc < NCHUNK; cc += 8) {
        float e[8];
        #pragma unroll
        for (int i = 0; i < 8; ++i)
            e[i] = E[(size_t)(cc + i) * DIM_N + n];
        #pragma unroll
        for (int i = 0; i < 8; ++i) {
            Cin[(size_t)(cc + i) * DIM_N + n] = cin;
            cin = fmaf(lT, cin, e[i]);
        }
    }
}

// writes tf32-rounded H (consumed only as GEMM2's A operand)
__global__ void scan_apply(const float* __restrict__ Bmat,
                           const float* __restrict__ lam,
                           const float* __restrict__ Cin,
                           float* __restrict__ H)
{
    const int n = (blockIdx.x * blockDim.x + threadIdx.x) * 2;
    const int cc = blockIdx.y;
    const float2 l2 = *(const float2*)(lam + n);
    const float* p = Bmat + (size_t)cc * CHUNK * DIM_N + n;
    float*       q = H    + (size_t)cc * CHUNK * DIM_N + n;
    float2 h2 = *(const float2*)(Cin + (size_t)cc * DIM_N + n);
    #pragma unroll 16
    for (int t = 0; t < CHUNK; ++t) {
        const float2 b = *(const float2*)(p + (size_t)t * DIM_N);
        h2.x = fmaf(l2.x, h2.x, b.x);
        h2.y = fmaf(l2.y, h2.y, b.y);
        float2 o;
        o.x = __uint_as_float(f2tf32(h2.x));
        o.y = __uint_as_float(f2tf32(h2.y));
        *(float2*)(q + (size_t)t * DIM_N) = o;
    }
}

// ---------------------------------------------------------------------------
extern "C" void kernel_launch(void* const* d_in, const int* in_sizes, int n_in,
                              void* d_out, int out_size)
{
    const float* xs     = (const float*)d_in[0];   // [SEQ_L, DIM_I]
    const float* lam    = (const float*)d_in[1];   // [DIM_N]
    const float* w_in   = (const float*)d_in[2];   // [DIM_N, DIM_I]
    const float* c_out  = (const float*)d_in[3];   // [DIM_I, DIM_N]
    const float* d_skip = (const float*)d_in[4];   // [DIM_I]
    float* out = (float*)d_out;                    // [SEQ_L, DIM_I]

    float *Bp, *Hp, *Ep, *Cp, *Xc, *Wc, *Cc;
    cudaGetSymbolAddress((void**)&Bp, g_B);
    cudaGetSymbolAddress((void**)&Hp, g_H);
    cudaGetSymbolAddress((void**)&Ep, g_E);
    cudaGetSymbolAddress((void**)&Cp, g_Cin);
    cudaGetSymbolAddress((void**)&Xc, g_Xc);
    cudaGetSymbolAddress((void**)&Wc, g_Wc);
    cudaGetSymbolAddress((void**)&Cc, g_Cc);

    const int SMEM_DYN = 3 * 32768;   // 96 KB
    cudaFuncSetAttribute(gemm_g1,
        cudaFuncAttributeMaxDynamicSharedMemorySize, SMEM_DYN);
    cudaFuncSetAttribute(gemm_g2,
        cudaFuncAttributeMaxDynamicSharedMemorySize, SMEM_DYN);

    // Pre-round operands to tf32 (single launch)
    {
        const int na4 = SEQ_L * DIM_I / 4;
        const int nb4 = DIM_N * DIM_I / 4;
        const int nc4 = DIM_I * DIM_N / 4;
        const int tot = na4 + nb4 + nc4;
        cvt3_tf32_kernel<<<(tot + 255) / 256, 256>>>(
            (const float4*)xs,    (float4*)Xc, na4,
            (const float4*)w_in,  (float4*)Wc, nb4,
            (const float4*)c_out, (float4*)Cc, nc4);
    }

    // GEMM1: B = xs @ w_in^T  (+ fused per-chunk scan tails E)
    dim3 g1(DIM_N / 128, SEQ_L / 128);
    gemm_g1<<<g1, 128, SMEM_DYN>>>(Xc, Wc, Bp, lam, Ep, SEQ_L, DIM_N, DIM_I);

    // Scan: carries across chunks, then apply (writes tf32-rounded H)
    scan_carry<<<DIM_N / 256, 256>>>(lam, Ep, Cp);
    dim3 gs(DIM_N / 512, NCHUNK);
    scan_apply<<<gs, 256>>>(Bp, lam, Cp, Hp);

    // GEMM2 (persistent): out = H @ c_out^T + xs * d_skip
    gemm_g2<<<GRID_P, 128, SMEM_DYN>>>(Hp, Cc, out, xs, d_skip,
                                       SEQ_L, DIM_I, DIM_N);
}

// round 13
// speedup vs baseline: 1.1169x; 1.0233x over previous
#include <cuda_runtime.h>
#include <cstdint>

#define SEQ_L  16384
#define DIM_I  2048
#define DIM_N  2048
#define CHUNK  128
#define NCHUNK (SEQ_L / CHUNK)
#define GRID_P 296

// Scratch (device globals — no allocation allowed in kernel_launch)
__device__ __align__(256) float g_B  [(size_t)SEQ_L  * DIM_N];
__device__ __align__(256) float g_H  [(size_t)SEQ_L  * DIM_N];
__device__ __align__(256) float g_E  [(size_t)NCHUNK * DIM_N];
__device__ __align__(256) float g_Cin[(size_t)NCHUNK * DIM_N];
__device__ __align__(256) float g_Xc [(size_t)SEQ_L  * DIM_I];
__device__ __align__(256) float g_Wc [(size_t)DIM_N  * DIM_I];
__device__ __align__(256) float g_Cc [(size_t)DIM_I  * DIM_N];

__device__ __forceinline__ uint32_t f2tf32(float f) {
    uint32_t u;
    asm("cvt.rna.tf32.f32 %0, %1;" : "=r"(u) : "f"(f));
    return u;
}
__device__ __forceinline__ uint32_t smem_u32(const void* p) {
    uint32_t a;
    asm("{ .reg .u64 t; cvta.to.shared.u64 t, %1; cvt.u32.u64 %0, t; }"
        : "=r"(a) : "l"(p));
    return a;
}

// ---------------------------------------------------------------------------
// Shared GEMM inner-loop macros. Each kernel using them must declare locals:
//   uint32_t af[2][4][4], bf[2][8][2];  float acc[4][8][4];
//   uint32_t arow[4], brow[8];  int g, c;
// ---------------------------------------------------------------------------
#define LOAD_FRAGS(buf, kc, sA, sB) do {                                      \
    const uint32_t _x0 = (uint32_t)(((2 * (kc))     ^ g) * 4 + c);            \
    const uint32_t _x1 = (uint32_t)(((2 * (kc) + 1) ^ g) * 4 + c);            \
    _Pragma("unroll")                                                         \
    for (int _mt = 0; _mt < 4; ++_mt) {                                       \
        af[buf][_mt][0] = (sA)[arow[_mt] + _x0];                              \
        af[buf][_mt][1] = (sA)[arow[_mt] + 256 + _x0];                        \
        af[buf][_mt][2] = (sA)[arow[_mt] + _x1];                              \
        af[buf][_mt][3] = (sA)[arow[_mt] + 256 + _x1];                        \
    }                                                                         \
    _Pragma("unroll")                                                         \
    for (int _nt = 0; _nt < 8; ++_nt) {                                       \
        bf[buf][_nt][0] = (sB)[brow[_nt] + _x0];                              \
        bf[buf][_nt][1] = (sB)[brow[_nt] + _x1];                              \
    }                                                                         \
  } while (0)

#define MMA_KC(cur) do {                                                      \
    _Pragma("unroll")                                                         \
    for (int _mt = 0; _mt < 4; ++_mt)                                         \
        _Pragma("unroll")                                                     \
        for (int _nt = 0; _nt < 8; ++_nt) {                                   \
            asm volatile(                                                     \
                "mma.sync.aligned.m16n8k8.row.col.f32.tf32.tf32.f32 "         \
                "{%0,%1,%2,%3}, {%4,%5,%6,%7}, {%8,%9}, {%0,%1,%2,%3};"       \
                : "+f"(acc[_mt][_nt][0]), "+f"(acc[_mt][_nt][1]),             \
                  "+f"(acc[_mt][_nt][2]), "+f"(acc[_mt][_nt][3])              \
                : "r"(af[cur][_mt][0]), "r"(af[cur][_mt][1]),                 \
                  "r"(af[cur][_mt][2]), "r"(af[cur][_mt][3]),                 \
                  "r"(bf[cur][_nt][0]), "r"(bf[cur][_nt][1]));                \
        }                                                                     \
  } while (0)

// ---------------------------------------------------------------------------
// One-shot tf32 rounding of all three operands (grid-partitioned)
// ---------------------------------------------------------------------------
__global__ void cvt3_tf32_kernel(const float4* __restrict__ a, float4* __restrict__ oa, int na4,
                                 const float4* __restrict__ b, float4* __restrict__ ob, int nb4,
                                 const float4* __restrict__ cc, float4* __restrict__ oc, int nc4)
{
    int i = blockIdx.x * blockDim.x + threadIdx.x;
    const float4* in; float4* out; int idx;
    if (i < na4)            { in = a;  out = oa; idx = i; }
    else if (i < na4 + nb4) { in = b;  out = ob; idx = i - na4; }
    else if (i < na4 + nb4 + nc4) { in = cc; out = oc; idx = i - na4 - nb4; }
    else return;
    float4 v = in[idx];
    float4 o;
    o.x = __uint_as_float(f2tf32(v.x));
    o.y = __uint_as_float(f2tf32(v.y));
    o.z = __uint_as_float(f2tf32(v.z));
    o.w = __uint_as_float(f2tf32(v.w));
    out[idx] = o;
}

// ---------------------------------------------------------------------------
// GEMM1 (waved): B = A*Bm^T + fused per-chunk scan tails E.
// CTA 128x128, BK=32, 4 warps (2x2), warp tile 64x64, 3-stage cp.async,
// XOR swizzle, 2 CTAs/SM. Iteration head reordered: first fragment load
// precedes the cp.async issue burst so fills hide under the mma stream.
// ---------------------------------------------------------------------------
__global__ void __launch_bounds__(128)
gemm_g1(const float* __restrict__ A, const float* __restrict__ Bm,
        float* __restrict__ C,
        const float* __restrict__ lam, float* __restrict__ E,
        int M, int Nn, int K)
{
    constexpr int BK = 32, STAGES = 3;
    extern __shared__ uint32_t smp[];

    const int tid    = threadIdx.x;
    const int lane   = tid & 31;
    const int wid    = tid >> 5;
    const int warp_m = wid & 1;
    const int warp_n = wid >> 1;
    const int g      = lane >> 2;
    const int c      = lane & 3;

    const int m0 = blockIdx.y * 128;
    const int n0 = blockIdx.x * 128;

    const int frow = tid >> 3;
    const int fu   = tid & 7;
    const int r7   = frow & 7;
    const float* Ag = A  + (size_t)(m0 + frow) * K + fu * 4;
    const float* Bg = Bm + (size_t)(n0 + frow) * K + fu * 4;
    const size_t rstep = (size_t)16 * K;

    const uint32_t sbw = smem_u32(smp);
    uint32_t dsto[8];
    #pragma unroll
    for (int i = 0; i < 8; ++i)
        dsto[i] = (uint32_t)(frow + i * 16) * 128u + (uint32_t)((fu ^ r7) << 4);

#define ISSUE_STAGE(st, kt) do {                                              \
    const uint32_t _bse = sbw + (uint32_t)(st) * 32768u;                      \
    const float* _ppa = Ag + (size_t)(kt) * BK;                               \
    const float* _ppb = Bg + (size_t)(kt) * BK;                               \
    _Pragma("unroll")                                                         \
    for (int _i = 0; _i < 8; ++_i) {                                          \
        asm volatile("cp.async.cg.shared.global [%0], [%1], 16;"              \
            :: "r"(_bse + dsto[_i]), "l"(_ppa + _i * rstep) : "memory");      \
        asm volatile("cp.async.cg.shared.global [%0], [%1], 16;"              \
            :: "r"(_bse + 16384u + dsto[_i]), "l"(_ppb + _i * rstep) : "memory"); \
    }                                                                         \
    asm volatile("cp.async.commit_group;" ::: "memory");                      \
  } while (0)

    uint32_t arow[4], brow[8];
    #pragma unroll
    for (int mt = 0; mt < 4; ++mt)
        arow[mt] = (uint32_t)(warp_m * 64 + mt * 16 + g) * 32u;
    #pragma unroll
    for (int nt = 0; nt < 8; ++nt)
        brow[nt] = (uint32_t)(warp_n * 64 + nt * 8 + g) * 32u;

    float acc[4][8][4];
    #pragma unroll
    for (int mt = 0; mt < 4; ++mt)
        #pragma unroll
        for (int nt = 0; nt < 8; ++nt)
            #pragma unroll
            for (int r = 0; r < 4; ++r) acc[mt][nt][r] = 0.f;

    const int KT = K / BK;

    ISSUE_STAGE(0, 0);
    ISSUE_STAGE(1, 1);

    uint32_t af[2][4][4], bf[2][8][2];

    for (int kt = 0; kt < KT; ++kt) {
        asm volatile("cp.async.wait_group 1;" ::: "memory");
        __syncthreads();

        const uint32_t* sA = smp + (kt % STAGES) * 8192;
        const uint32_t* sB = sA + 4096;

        LOAD_FRAGS(0, 0, sA, sB);           // start mma dependency chain first
        if (kt + 2 < KT) ISSUE_STAGE((kt + 2) % STAGES, kt + 2);

        #pragma unroll
        for (int kc = 0; kc < 4; ++kc) {
            const int cur = kc & 1;
            if (kc < 3) LOAD_FRAGS(cur ^ 1, kc + 1, sA, sB);
            MMA_KC(cur);
        }
    }
#undef ISSUE_STAGE

    // epilogue: write C
    #pragma unroll
    for (int mt = 0; mt < 4; ++mt) {
        const int r0 = m0 + warp_m * 64 + mt * 16 + g;
        const int r1 = r0 + 8;
        float* p0 = C + (size_t)r0 * Nn;
        float* p1 = C + (size_t)r1 * Nn;
        #pragma unroll
        for (int nt = 0; nt < 8; ++nt) {
            const int col = n0 + warp_n * 64 + nt * 8 + c * 2;
            *(float2*)(p0 + col) = make_float2(acc[mt][nt][0], acc[mt][nt][1]);
            *(float2*)(p1 + col) = make_float2(acc[mt][nt][2], acc[mt][nt][3]);
        }
    }

    // fused scan_chunk_reduce: this m-tile IS scan chunk m0/128
    __syncthreads();
    float* st = (float*)smp;
    #pragma unroll
    for (int mt = 0; mt < 4; ++mt) {
        const int lr0 = warp_m * 64 + mt * 16 + g;
        #pragma unroll
        for (int nt = 0; nt < 8; ++nt) {
            const int lc = warp_n * 64 + nt * 8 + c * 2;
            *(float2*)&st[(size_t)lr0 * 132 + lc] =
                make_float2(acc[mt][nt][0], acc[mt][nt][1]);
            *(float2*)&st[(size_t)(lr0 + 8) * 132 + lc] =
                make_float2(acc[mt][nt][2], acc[mt][nt][3]);
        }
    }
    __syncthreads();
    const float l = lam[n0 + tid];
    float h = 0.f;
    #pragma unroll 16
    for (int t = 0; t < 128; ++t)
        h = fmaf(l, h, st[(size_t)t * 132 + tid]);
    E[(size_t)(m0 >> 7) * DIM_N + n0 + tid] = h;
}

// ---------------------------------------------------------------------------
// GEMM2 (persistent): out = A*Bm^T + sx*sd. Same hot loop; grid 296 (2/SM),
// cp.async ring carried continuously across tiles (running stage counters).
// ---------------------------------------------------------------------------
__global__ void __launch_bounds__(128)
gemm_g2(const float* __restrict__ A, const float* __restrict__ Bm,
        float* __restrict__ C, const float* __restrict__ sx,
        const float* __restrict__ sd, int M, int Nn, int K)
{
    constexpr int BK = 32;
    extern __shared__ uint32_t smp[];

    const int tid    = threadIdx.x;
    const int lane   = tid & 31;
    const int wid    = tid >> 5;
    const int warp_m = wid & 1;
    const int warp_n = wid >> 1;
    const int g      = lane >> 2;
    const int c      = lane & 3;

    const int NBN    = Nn / 128;
    const int NTILES = (M / 128) * NBN;

    const int frow = tid >> 3;
    const int fu   = tid & 7;
    const int r7   = frow & 7;
    const size_t rstep = (size_t)16 * K;

    const uint32_t sbw = smem_u32(smp);
    uint32_t dsto[8];
    #pragma unroll
    for (int i = 0; i < 8; ++i)
        dsto[i] = (uint32_t)(frow + i * 16) * 128u + (uint32_t)((fu ^ r7) << 4);

#define ISSUE_PTR(pa_, pb_, st) do {                                          \
    const uint32_t _bse = sbw + (uint32_t)(st) * 32768u;                      \
    const float* _ppa = (pa_);                                                \
    const float* _ppb = (pb_);                                                \
    _Pragma("unroll")                                                         \
    for (int _i = 0; _i < 8; ++_i) {                                          \
        asm volatile("cp.async.cg.shared.global [%0], [%1], 16;"              \
            :: "r"(_bse + dsto[_i]), "l"(_ppa + _i * rstep) : "memory");      \
        asm volatile("cp.async.cg.shared.global [%0], [%1], 16;"              \
            :: "r"(_bse + 16384u + dsto[_i]), "l"(_ppb + _i * rstep) : "memory"); \
    }                                                                         \
    asm volatile("cp.async.commit_group;" ::: "memory");                      \
  } while (0)

    uint32_t arow[4], brow[8];
    #pragma unroll
    for (int mt = 0; mt < 4; ++mt)
        arow[mt] = (uint32_t)(warp_m * 64 + mt * 16 + g) * 32u;
    #pragma unroll
    for (int nt = 0; nt < 8; ++nt)
        brow[nt] = (uint32_t)(warp_n * 64 + nt * 8 + g) * 32u;

    float acc[4][8][4];
    #pragma unroll
    for (int mt = 0; mt < 4; ++mt)
        #pragma unroll
        for (int nt = 0; nt < 8; ++nt)
            #pragma unroll
            for (int r = 0; r < 4; ++r) acc[mt][nt][r] = 0.f;

    uint32_t af[2][4][4], bf[2][8][2];

    const int bid = blockIdx.x;
    const int cnt = (NTILES - bid + GRID_P - 1) / GRID_P;
    if (cnt <= 0) return;

    // prologue: first two stages of first tile
    {
        const int m0 = (bid / NBN) * 128, n0 = (bid % NBN) * 128;
        const float* pA = A  + (size_t)(m0 + frow) * K + fu * 4;
        const float* pB = Bm + (size_t)(n0 + frow) * K + fu * 4;
        ISSUE_PTR(pA, pB, 0);
        ISSUE_PTR(pA + BK, pB + BK, 1);
    }

    int st_cur = 0, st_nxt = 2;

    for (int j = 0; j < cnt; ++j) {
        const int tile = bid + j * GRID_P;
        const int m0 = (tile / NBN) * 128;
        const int n0 = (tile % NBN) * 128;
        const float* curA = A  + (size_t)(m0 + frow) * K + fu * 4;
        const float* curB = Bm + (size_t)(n0 + frow) * K + fu * 4;

        for (int kt = 0; kt < 64; ++kt) {
            asm volatile("cp.async.wait_group 1;" ::: "memory");
            __syncthreads();

            const uint32_t* sA = smp + st_cur * 8192;
            const uint32_t* sB = sA + 4096;

            LOAD_FRAGS(0, 0, sA, sB);       // start mma dependency chain first

            if (kt + 2 < 64) {
                ISSUE_PTR(curA + (size_t)(kt + 2) * BK,
                          curB + (size_t)(kt + 2) * BK, st_nxt);
            } else if (j + 1 < cnt) {
                const int t2 = tile + GRID_P;
                const int m2 = (t2 / NBN) * 128, n2 = (t2 % NBN) * 128;
                const float* nA = A  + (size_t)(m2 + frow) * K + fu * 4
                                     + (size_t)(kt + 2 - 64) * BK;
                const float* nB = Bm + (size_t)(n2 + frow) * K + fu * 4
                                     + (size_t)(kt + 2 - 64) * BK;
                ISSUE_PTR(nA, nB, st_nxt);
            } else {
                asm volatile("cp.async.commit_group;" ::: "memory");
            }

            #pragma unroll
            for (int kc = 0; kc < 4; ++kc) {
                const int cur = kc & 1;
                if (kc < 3) LOAD_FRAGS(cur ^ 1, kc + 1, sA, sB);
                MMA_KC(cur);
            }

            st_cur = (st_cur == 2) ? 0 : st_cur + 1;
            st_nxt = (st_nxt == 2) ? 0 : st_nxt + 1;
        }

        // epilogue (registers + global only — smem stays owned by the ring)
        #pragma unroll
        for (int mt = 0; mt < 4; ++mt) {
            const int r0 = m0 + warp_m * 64 + mt * 16 + g;
            const int r1 = r0 + 8;
            float* p0 = C + (size_t)r0 * Nn;
            float* p1 = C + (size_t)r1 * Nn;
            #pragma unroll
            for (int nt = 0; nt < 8; ++nt) {
                const int col = n0 + warp_n * 64 + nt * 8 + c * 2;
                float2 v0 = make_float2(acc[mt][nt][0], acc[mt][nt][1]);
                float2 v1 = make_float2(acc[mt][nt][2], acc[mt][nt][3]);
                const float2 x0 = *(const float2*)(sx + (size_t)r0 * Nn + col);
                const float2 x1 = *(const float2*)(sx + (size_t)r1 * Nn + col);
                const float2 dd = *(const float2*)(sd + col);
                v0.x = fmaf(x0.x, dd.x, v0.x);
                v0.y = fmaf(x0.y, dd.y, v0.y);
                v1.x = fmaf(x1.x, dd.x, v1.x);
                v1.y = fmaf(x1.y, dd.y, v1.y);
                *(float2*)(p0 + col) = v0;
                *(float2*)(p1 + col) = v1;
                acc[mt][nt][0] = 0.f; acc[mt][nt][1] = 0.f;
                acc[mt][nt][2] = 0.f; acc[mt][nt][3] = 0.f;
            }
        }
    }
#undef ISSUE_PTR
}

// ---------------------------------------------------------------------------
// Scan combine: per-state carries across chunks, then apply (4 states/thread).
// ---------------------------------------------------------------------------
__global__ void scan_carry(const float* __restrict__ lam,
                           const float* __restrict__ E,
                           float* __restrict__ Cin)
{
    const int n = blockIdx.x * blockDim.x + threadIdx.x;
    const float l = lam[n];
    float lT = l;
    #pragma unroll
    for (int i = 0; i < 7; ++i) lT *= lT;   // l^128
    float cin = 0.f;
    for (int cc = 0; cc < NCHUNK; cc += 8) {
        float e[8];
        #pragma unroll
        for (int i = 0; i < 8; ++i)
            e[i] = E[(size_t)(cc + i) * DIM_N + n];
        #pragma unroll
        for (int i = 0; i < 8; ++i) {
            Cin[(size_t)(cc + i) * DIM_N + n] = cin;
            cin = fmaf(lT, cin, e[i]);
        }
    }
}

// writes tf32-rounded H (consumed only as GEMM2's A operand)
__global__ void scan_apply(const float* __restrict__ Bmat,
                           const float* __restrict__ lam,
                           const float* __restrict__ Cin,
                           float* __restrict__ H)
{
    const int n = (blockIdx.x * blockDim.x + threadIdx.x) * 4;
    const int cc = blockIdx.y;
    const float4 l4 = *(const float4*)(lam + n);
    const float* p = Bmat + (size_t)cc * CHUNK * DIM_N + n;
    float*       q = H    + (size_t)cc * CHUNK * DIM_N + n;
    float4 h4 = *(const float4*)(Cin + (size_t)cc * DIM_N + n);
    #pragma unroll 8
    for (int t = 0; t < CHUNK; ++t) {
        const float4 b = *(const float4*)(p + (size_t)t * DIM_N);
        h4.x = fmaf(l4.x, h4.x, b.x);
        h4.y = fmaf(l4.y, h4.y, b.y);
        h4.z = fmaf(l4.z, h4.z, b.z);
        h4.w = fmaf(l4.w, h4.w, b.w);
        float4 o;
        o.x = __uint_as_float(f2tf32(h4.x));
        o.y = __uint_as_float(f2tf32(h4.y));
        o.z = __uint_as_float(f2tf32(h4.z));
        o.w = __uint_as_float(f2tf32(h4.w));
        *(float4*)(q + (size_t)t * DIM_N) = o;
    }
}

// ---------------------------------------------------------------------------
extern "C" void kernel_launch(void* const* d_in, const int* in_sizes, int n_in,
                              void* d_out, int out_size)
{
    const float* xs     = (const float*)d_in[0];   // [SEQ_L, DIM_I]
    const float* lam    = (const float*)d_in[1];   // [DIM_N]
    const float* w_in   = (const float*)d_in[2];   // [DIM_N, DIM_I]
    const float* c_out  = (const float*)d_in[3];   // [DIM_I, DIM_N]
    const float* d_skip = (const float*)d_in[4];   // [DIM_I]
    float* out = (float*)d_out;                    // [SEQ_L, DIM_I]

    float *Bp, *Hp, *Ep, *Cp, *Xc, *Wc, *Cc;
    cudaGetSymbolAddress((void**)&Bp, g_B);
    cudaGetSymbolAddress((void**)&Hp, g_H);
    cudaGetSymbolAddress((void**)&Ep, g_E);
    cudaGetSymbolAddress((void**)&Cp, g_Cin);
    cudaGetSymbolAddress((void**)&Xc, g_Xc);
    cudaGetSymbolAddress((void**)&Wc, g_Wc);
    cudaGetSymbolAddress((void**)&Cc, g_Cc);

    const int SMEM_DYN = 3 * 32768;   // 96 KB
    cudaFuncSetAttribute(gemm_g1,
        cudaFuncAttributeMaxDynamicSharedMemorySize, SMEM_DYN);
    cudaFuncSetAttribute(gemm_g2,
        cudaFuncAttributeMaxDynamicSharedMemorySize, SMEM_DYN);

    // Pre-round operands to tf32 (single launch)
    {
        const int na4 = SEQ_L * DIM_I / 4;
        const int nb4 = DIM_N * DIM_I / 4;
        const int nc4 = DIM_I * DIM_N / 4;
        const int tot = na4 + nb4 + nc4;
        cvt3_tf32_kernel<<<(tot + 255) / 256, 256>>>(
            (const float4*)xs,    (float4*)Xc, na4,
            (const float4*)w_in,  (float4*)Wc, nb4,
            (const float4*)c_out, (float4*)Cc, nc4);
    }

    // GEMM1: B = xs @ w_in^T  (+ fused per-chunk scan tails E)
    dim3 g1(DIM_N / 128, SEQ_L / 128);
    gemm_g1<<<g1, 128, SMEM_DYN>>>(Xc, Wc, Bp, lam, Ep, SEQ_L, DIM_N, DIM_I);

    // Scan: carries across chunks, then apply (writes tf32-rounded H)
    scan_carry<<<DIM_N / 256, 256>>>(lam, Ep, Cp);
    dim3 gs(DIM_N / 1024, NCHUNK);
    scan_apply<<<gs, 256>>>(Bp, lam, Cp, Hp);

    // GEMM2 (persistent): out = H @ c_out^T + xs * d_skip
    gemm_g2<<<GRID_P, 128, SMEM_DYN>>>(Hp, Cc, out, xs, d_skip,
                                       SEQ_L, DIM_I, DIM_N);
}

// round 14
// speedup vs baseline: 1.1224x; 1.0049x over previous
#include <cuda_runtime.h>
#include <cstdint>

#define SEQ_L  16384
#define DIM_I  2048
#define DIM_N  2048
#define CHUNK  128
#define NCHUNK (SEQ_L / CHUNK)
#define GRID_P 296

// Scratch (device globals — no allocation allowed in kernel_launch)
__device__ __align__(256) float g_B  [(size_t)SEQ_L  * DIM_N];
__device__ __align__(256) float g_H  [(size_t)SEQ_L  * DIM_N];
__device__ __align__(256) float g_E  [(size_t)NCHUNK * DIM_N];
__device__ __align__(256) float g_Cin[(size_t)NCHUNK * DIM_N];
__device__ __align__(256) float g_Xc [(size_t)SEQ_L  * DIM_I];
__device__ __align__(256) float g_Wc [(size_t)DIM_N  * DIM_I];
__device__ __align__(256) float g_Cc [(size_t)DIM_I  * DIM_N];

__device__ __forceinline__ uint32_t f2tf32(float f) {
    uint32_t u;
    asm("cvt.rna.tf32.f32 %0, %1;" : "=r"(u) : "f"(f));
    return u;
}
__device__ __forceinline__ uint32_t smem_u32(const void* p) {
    uint32_t a;
    asm("{ .reg .u64 t; cvta.to.shared.u64 t, %1; cvt.u32.u64 %0, t; }"
        : "=r"(a) : "l"(p));
    return a;
}

// ---------------------------------------------------------------------------
// Shared GEMM inner-loop macros. Each kernel using them must declare locals:
//   uint32_t af[2][4][4], bf[2][8][2];  float acc[4][8][4];
//   uint32_t arow[4], brow[8];  int g, c;
// ---------------------------------------------------------------------------
#define LOAD_FRAGS(buf, kc, sA, sB) do {                                      \
    const uint32_t _x0 = (uint32_t)(((2 * (kc))     ^ g) * 4 + c);            \
    const uint32_t _x1 = (uint32_t)(((2 * (kc) + 1) ^ g) * 4 + c);            \
    _Pragma("unroll")                                                         \
    for (int _mt = 0; _mt < 4; ++_mt) {                                       \
        af[buf][_mt][0] = (sA)[arow[_mt] + _x0];                              \
        af[buf][_mt][1] = (sA)[arow[_mt] + 256 + _x0];                        \
        af[buf][_mt][2] = (sA)[arow[_mt] + _x1];                              \
        af[buf][_mt][3] = (sA)[arow[_mt] + 256 + _x1];                        \
    }                                                                         \
    _Pragma("unroll")                                                         \
    for (int _nt = 0; _nt < 8; ++_nt) {                                       \
        bf[buf][_nt][0] = (sB)[brow[_nt] + _x0];                              \
        bf[buf][_nt][1] = (sB)[brow[_nt] + _x1];                              \
    }                                                                         \
  } while (0)

#define MMA_KC(cur) do {                                                      \
    _Pragma("unroll")                                                         \
    for (int _mt = 0; _mt < 4; ++_mt)                                         \
        _Pragma("unroll")                                                     \
        for (int _nt = 0; _nt < 8; ++_nt) {                                   \
            asm volatile(                                                     \
                "mma.sync.aligned.m16n8k8.row.col.f32.tf32.tf32.f32 "         \
                "{%0,%1,%2,%3}, {%4,%5,%6,%7}, {%8,%9}, {%0,%1,%2,%3};"       \
                : "+f"(acc[_mt][_nt][0]), "+f"(acc[_mt][_nt][1]),             \
                  "+f"(acc[_mt][_nt][2]), "+f"(acc[_mt][_nt][3])              \
                : "r"(af[cur][_mt][0]), "r"(af[cur][_mt][1]),                 \
                  "r"(af[cur][_mt][2]), "r"(af[cur][_mt][3]),                 \
                  "r"(bf[cur][_nt][0]), "r"(bf[cur][_nt][1]));                \
        }                                                                     \
  } while (0)

// ---------------------------------------------------------------------------
// One-shot tf32 rounding of all three operands (grid-partitioned)
// ---------------------------------------------------------------------------
__global__ void cvt3_tf32_kernel(const float4* __restrict__ a, float4* __restrict__ oa, int na4,
                                 const float4* __restrict__ b, float4* __restrict__ ob, int nb4,
                                 const float4* __restrict__ cc, float4* __restrict__ oc, int nc4)
{
    int i = blockIdx.x * blockDim.x + threadIdx.x;
    const float4* in; float4* out; int idx;
    if (i < na4)            { in = a;  out = oa; idx = i; }
    else if (i < na4 + nb4) { in = b;  out = ob; idx = i - na4; }
    else if (i < na4 + nb4 + nc4) { in = cc; out = oc; idx = i - na4 - nb4; }
    else return;
    float4 v = in[idx];
    float4 o;
    o.x = __uint_as_float(f2tf32(v.x));
    o.y = __uint_as_float(f2tf32(v.y));
    o.z = __uint_as_float(f2tf32(v.z));
    o.w = __uint_as_float(f2tf32(v.w));
    out[idx] = o;
}

// ---------------------------------------------------------------------------
// GEMM1 (waved): B = A*Bm^T + fused per-chunk scan tails E.
// CTA 128x128, BK=32, 4 warps (2x2), warp tile 64x64, 3-stage cp.async,
// XOR swizzle, 2 CTAs/SM. Head reordered: first fragment load precedes the
// cp.async issue burst so fills hide under the mma stream.
// ---------------------------------------------------------------------------
__global__ void __launch_bounds__(128)
gemm_g1(const float* __restrict__ A, const float* __restrict__ Bm,
        float* __restrict__ C,
        const float* __restrict__ lam, float* __restrict__ E,
        int M, int Nn, int K)
{
    constexpr int BK = 32, STAGES = 3;
    extern __shared__ uint32_t smp[];

    const int tid    = threadIdx.x;
    const int lane   = tid & 31;
    const int wid    = tid >> 5;
    const int warp_m = wid & 1;
    const int warp_n = wid >> 1;
    const int g      = lane >> 2;
    const int c      = lane & 3;

    const int m0 = blockIdx.y * 128;
    const int n0 = blockIdx.x * 128;

    const int frow = tid >> 3;
    const int fu   = tid & 7;
    const int r7   = frow & 7;
    const float* Ag = A  + (size_t)(m0 + frow) * K + fu * 4;
    const float* Bg = Bm + (size_t)(n0 + frow) * K + fu * 4;
    const size_t rstep = (size_t)16 * K;

    const uint32_t sbw = smem_u32(smp);
    uint32_t dsto[8];
    #pragma unroll
    for (int i = 0; i < 8; ++i)
        dsto[i] = (uint32_t)(frow + i * 16) * 128u + (uint32_t)((fu ^ r7) << 4);

#define ISSUE_STAGE(st, kt) do {                                              \
    const uint32_t _bse = sbw + (uint32_t)(st) * 32768u;                      \
    const float* _ppa = Ag + (size_t)(kt) * BK;                               \
    const float* _ppb = Bg + (size_t)(kt) * BK;                               \
    _Pragma("unroll")                                                         \
    for (int _i = 0; _i < 8; ++_i) {                                          \
        asm volatile("cp.async.cg.shared.global [%0], [%1], 16;"              \
            :: "r"(_bse + dsto[_i]), "l"(_ppa + _i * rstep) : "memory");      \
        asm volatile("cp.async.cg.shared.global [%0], [%1], 16;"              \
            :: "r"(_bse + 16384u + dsto[_i]), "l"(_ppb + _i * rstep) : "memory"); \
    }                                                                         \
    asm volatile("cp.async.commit_group;" ::: "memory");                      \
  } while (0)

    uint32_t arow[4], brow[8];
    #pragma unroll
    for (int mt = 0; mt < 4; ++mt)
        arow[mt] = (uint32_t)(warp_m * 64 + mt * 16 + g) * 32u;
    #pragma unroll
    for (int nt = 0; nt < 8; ++nt)
        brow[nt] = (uint32_t)(warp_n * 64 + nt * 8 + g) * 32u;

    float acc[4][8][4];
    #pragma unroll
    for (int mt = 0; mt < 4; ++mt)
        #pragma unroll
        for (int nt = 0; nt < 8; ++nt)
            #pragma unroll
            for (int r = 0; r < 4; ++r) acc[mt][nt][r] = 0.f;

    const int KT = K / BK;

    ISSUE_STAGE(0, 0);
    ISSUE_STAGE(1, 1);

    uint32_t af[2][4][4], bf[2][8][2];

    for (int kt = 0; kt < KT; ++kt) {
        asm volatile("cp.async.wait_group 1;" ::: "memory");
        __syncthreads();

        const uint32_t* sA = smp + (kt % STAGES) * 8192;
        const uint32_t* sB = sA + 4096;

        LOAD_FRAGS(0, 0, sA, sB);           // start mma dependency chain first
        if (kt + 2 < KT) ISSUE_STAGE((kt + 2) % STAGES, kt + 2);

        #pragma unroll
        for (int kc = 0; kc < 4; ++kc) {
            const int cur = kc & 1;
            if (kc < 3) LOAD_FRAGS(cur ^ 1, kc + 1, sA, sB);
            MMA_KC(cur);
        }
    }
#undef ISSUE_STAGE

    // epilogue: write C
    #pragma unroll
    for (int mt = 0; mt < 4; ++mt) {
        const int r0 = m0 + warp_m * 64 + mt * 16 + g;
        const int r1 = r0 + 8;
        float* p0 = C + (size_t)r0 * Nn;
        float* p1 = C + (size_t)r1 * Nn;
        #pragma unroll
        for (int nt = 0; nt < 8; ++nt) {
            const int col = n0 + warp_n * 64 + nt * 8 + c * 2;
            *(float2*)(p0 + col) = make_float2(acc[mt][nt][0], acc[mt][nt][1]);
            *(float2*)(p1 + col) = make_float2(acc[mt][nt][2], acc[mt][nt][3]);
        }
    }

    // fused scan_chunk_reduce: this m-tile IS scan chunk m0/128
    __syncthreads();
    float* st = (float*)smp;
    #pragma unroll
    for (int mt = 0; mt < 4; ++mt) {
        const int lr0 = warp_m * 64 + mt * 16 + g;
        #pragma unroll
        for (int nt = 0; nt < 8; ++nt) {
            const int lc = warp_n * 64 + nt * 8 + c * 2;
            *(float2*)&st[(size_t)lr0 * 132 + lc] =
                make_float2(acc[mt][nt][0], acc[mt][nt][1]);
            *(float2*)&st[(size_t)(lr0 + 8) * 132 + lc] =
                make_float2(acc[mt][nt][2], acc[mt][nt][3]);
        }
    }
    __syncthreads();
    const float l = lam[n0 + tid];
    float h = 0.f;
    #pragma unroll 16
    for (int t = 0; t < 128; ++t)
        h = fmaf(l, h, st[(size_t)t * 132 + tid]);
    E[(size_t)(m0 >> 7) * DIM_N + n0 + tid] = h;
}

// ---------------------------------------------------------------------------
// GEMM2 (persistent): out = A*Bm^T + sx*sd. Same hot loop; grid 296 (2/SM),
// cp.async ring carried continuously across tiles (running stage counters).
// ---------------------------------------------------------------------------
__global__ void __launch_bounds__(128)
gemm_g2(const float* __restrict__ A, const float* __restrict__ Bm,
        float* __restrict__ C, const float* __restrict__ sx,
        const float* __restrict__ sd, int M, int Nn, int K)
{
    constexpr int BK = 32;
    extern __shared__ uint32_t smp[];

    const int tid    = threadIdx.x;
    const int lane   = tid & 31;
    const int wid    = tid >> 5;
    const int warp_m = wid & 1;
    const int warp_n = wid >> 1;
    const int g      = lane >> 2;
    const int c      = lane & 3;

    const int NBN    = Nn / 128;
    const int NTILES = (M / 128) * NBN;

    const int frow = tid >> 3;
    const int fu   = tid & 7;
    const int r7   = frow & 7;
    const size_t rstep = (size_t)16 * K;

    const uint32_t sbw = smem_u32(smp);
    uint32_t dsto[8];
    #pragma unroll
    for (int i = 0; i < 8; ++i)
        dsto[i] = (uint32_t)(frow + i * 16) * 128u + (uint32_t)((fu ^ r7) << 4);

#define ISSUE_PTR(pa_, pb_, st) do {                                          \
    const uint32_t _bse = sbw + (uint32_t)(st) * 32768u;                      \
    const float* _ppa = (pa_);                                                \
    const float* _ppb = (pb_);                                                \
    _Pragma("unroll")                                                         \
    for (int _i = 0; _i < 8; ++_i) {                                          \
        asm volatile("cp.async.cg.shared.global [%0], [%1], 16;"              \
            :: "r"(_bse + dsto[_i]), "l"(_ppa + _i * rstep) : "memory");      \
        asm volatile("cp.async.cg.shared.global [%0], [%1], 16;"              \
            :: "r"(_bse + 16384u + dsto[_i]), "l"(_ppb + _i * rstep) : "memory"); \
    }                                                                         \
    asm volatile("cp.async.commit_group;" ::: "memory");                      \
  } while (0)

    uint32_t arow[4], brow[8];
    #pragma unroll
    for (int mt = 0; mt < 4; ++mt)
        arow[mt] = (uint32_t)(warp_m * 64 + mt * 16 + g) * 32u;
    #pragma unroll
    for (int nt = 0; nt < 8; ++nt)
        brow[nt] = (uint32_t)(warp_n * 64 + nt * 8 + g) * 32u;

    float acc[4][8][4];
    #pragma unroll
    for (int mt = 0; mt < 4; ++mt)
        #pragma unroll
        for (int nt = 0; nt < 8; ++nt)
            #pragma unroll
            for (int r = 0; r < 4; ++r) acc[mt][nt][r] = 0.f;

    uint32_t af[2][4][4], bf[2][8][2];

    const int bid = blockIdx.x;
    const int cnt = (NTILES - bid + GRID_P - 1) / GRID_P;
    if (cnt <= 0) return;

    // prologue: first two stages of first tile
    {
        const int m0 = (bid / NBN) * 128, n0 = (bid % NBN) * 128;
        const float* pA = A  + (size_t)(m0 + frow) * K + fu * 4;
        const float* pB = Bm + (size_t)(n0 + frow) * K + fu * 4;
        ISSUE_PTR(pA, pB, 0);
        ISSUE_PTR(pA + BK, pB + BK, 1);
    }

    int st_cur = 0, st_nxt = 2;

    for (int j = 0; j < cnt; ++j) {
        const int tile = bid + j * GRID_P;
        const int m0 = (tile / NBN) * 128;
        const int n0 = (tile % NBN) * 128;
        const float* curA = A  + (size_t)(m0 + frow) * K + fu * 4;
        const float* curB = Bm + (size_t)(n0 + frow) * K + fu * 4;

        for (int kt = 0; kt < 64; ++kt) {
            asm volatile("cp.async.wait_group 1;" ::: "memory");
            __syncthreads();

            const uint32_t* sA = smp + st_cur * 8192;
            const uint32_t* sB = sA + 4096;

            LOAD_FRAGS(0, 0, sA, sB);       // start mma dependency chain first

            if (kt + 2 < 64) {
                ISSUE_PTR(curA + (size_t)(kt + 2) * BK,
                          curB + (size_t)(kt + 2) * BK, st_nxt);
            } else if (j + 1 < cnt) {
                const int t2 = tile + GRID_P;
                const int m2 = (t2 / NBN) * 128, n2 = (t2 % NBN) * 128;
                const float* nA = A  + (size_t)(m2 + frow) * K + fu * 4
                                     + (size_t)(kt + 2 - 64) * BK;
                const float* nB = Bm + (size_t)(n2 + frow) * K + fu * 4
                                     + (size_t)(kt + 2 - 64) * BK;
                ISSUE_PTR(nA, nB, st_nxt);
            } else {
                asm volatile("cp.async.commit_group;" ::: "memory");
            }

            #pragma unroll
            for (int kc = 0; kc < 4; ++kc) {
                const int cur = kc & 1;
                if (kc < 3) LOAD_FRAGS(cur ^ 1, kc + 1, sA, sB);
                MMA_KC(cur);
            }

            st_cur = (st_cur == 2) ? 0 : st_cur + 1;
            st_nxt = (st_nxt == 2) ? 0 : st_nxt + 1;
        }

        // epilogue (registers + global only — smem stays owned by the ring)
        #pragma unroll
        for (int mt = 0; mt < 4; ++mt) {
            const int r0 = m0 + warp_m * 64 + mt * 16 + g;
            const int r1 = r0 + 8;
            float* p0 = C + (size_t)r0 * Nn;
            float* p1 = C + (size_t)r1 * Nn;
            #pragma unroll
            for (int nt = 0; nt < 8; ++nt) {
                const int col = n0 + warp_n * 64 + nt * 8 + c * 2;
                float2 v0 = make_float2(acc[mt][nt][0], acc[mt][nt][1]);
                float2 v1 = make_float2(acc[mt][nt][2], acc[mt][nt][3]);
                const float2 x0 = *(const float2*)(sx + (size_t)r0 * Nn + col);
                const float2 x1 = *(const float2*)(sx + (size_t)r1 * Nn + col);
                const float2 dd = *(const float2*)(sd + col);
                v0.x = fmaf(x0.x, dd.x, v0.x);
                v0.y = fmaf(x0.y, dd.y, v0.y);
                v1.x = fmaf(x1.x, dd.x, v1.x);
                v1.y = fmaf(x1.y, dd.y, v1.y);
                *(float2*)(p0 + col) = v0;
                *(float2*)(p1 + col) = v1;
                acc[mt][nt][0] = 0.f; acc[mt][nt][1] = 0.f;
                acc[mt][nt][2] = 0.f; acc[mt][nt][3] = 0.f;
            }
        }
    }
#undef ISSUE_PTR
}

// ---------------------------------------------------------------------------
// Scan combine: per-state carries across chunks, then apply (2 states/thread —
// measured-best: 38us @ 72% HBM; float4 variant regressed to 45us).
// ---------------------------------------------------------------------------
__global__ void scan_carry(const float* __restrict__ lam,
                           const float* __restrict__ E,
                           float* __restrict__ Cin)
{
    const int n = blockIdx.x * blockDim.x + threadIdx.x;
    const float l = lam[n];
    float lT = l;
    #pragma unroll
    for (int i = 0; i < 7; ++i) lT *= lT;   // l^128
    float cin = 0.f;
    for (int cc = 0; cc < NCHUNK; cc += 8) {
        float e[8];
        #pragma unroll
        for (int i = 0; i < 8; ++i)
            e[i] = E[(size_t)(cc + i) * DIM_N + n];
        #pragma unroll
        for (int i = 0; i < 8; ++i) {
            Cin[(size_t)(cc + i) * DIM_N + n] = cin;
            cin = fmaf(lT, cin, e[i]);
        }
    }
}

// writes tf32-rounded H (consumed only as GEMM2's A operand)
__global__ void scan_apply(const float* __restrict__ Bmat,
                           const float* __restrict__ lam,
                           const float* __restrict__ Cin,
                           float* __restrict__ H)
{
    const int n = (blockIdx.x * blockDim.x + threadIdx.x) * 2;
    const int cc = blockIdx.y;
    const float2 l2 = *(const float2*)(lam + n);
    const float* p = Bmat + (size_t)cc * CHUNK * DIM_N + n;
    float*       q = H    + (size_t)cc * CHUNK * DIM_N + n;
    float2 h2 = *(const float2*)(Cin + (size_t)cc * DIM_N + n);
    #pragma unroll 16
    for (int t = 0; t < CHUNK; ++t) {
        const float2 b = *(const float2*)(p + (size_t)t * DIM_N);
        h2.x = fmaf(l2.x, h2.x, b.x);
        h2.y = fmaf(l2.y, h2.y, b.y);
        float2 o;
        o.x = __uint_as_float(f2tf32(h2.x));
        o.y = __uint_as_float(f2tf32(h2.y));
        *(float2*)(q + (size_t)t * DIM_N) = o;
    }
}

// ---------------------------------------------------------------------------
extern "C" void kernel_launch(void* const* d_in, const int* in_sizes, int n_in,
                              void* d_out, int out_size)
{
    const float* xs     = (const float*)d_in[0];   // [SEQ_L, DIM_I]
    const float* lam    = (const float*)d_in[1];   // [DIM_N]
    const float* w_in   = (const float*)d_in[2];   // [DIM_N, DIM_I]
    const float* c_out  = (const float*)d_in[3];   // [DIM_I, DIM_N]
    const float* d_skip = (const float*)d_in[4];   // [DIM_I]
    float* out = (float*)d_out;                    // [SEQ_L, DIM_I]

    float *Bp, *Hp, *Ep, *Cp, *Xc, *Wc, *Cc;
    cudaGetSymbolAddress((void**)&Bp, g_B);
    cudaGetSymbolAddress((void**)&Hp, g_H);
    cudaGetSymbolAddress((void**)&Ep, g_E);
    cudaGetSymbolAddress((void**)&Cp, g_Cin);
    cudaGetSymbolAddress((void**)&Xc, g_Xc);
    cudaGetSymbolAddress((void**)&Wc, g_Wc);
    cudaGetSymbolAddress((void**)&Cc, g_Cc);

    const int SMEM_DYN = 3 * 32768;   // 96 KB
    cudaFuncSetAttribute(gemm_g1,
        cudaFuncAttributeMaxDynamicSharedMemorySize, SMEM_DYN);
    cudaFuncSetAttribute(gemm_g2,
        cudaFuncAttributeMaxDynamicSharedMemorySize, SMEM_DYN);

    // Pre-round operands to tf32 (single launch)
    {
        const int na4 = SEQ_L * DIM_I / 4;
        const int nb4 = DIM_N * DIM_I / 4;
        const int nc4 = DIM_I * DIM_N / 4;
        const int tot = na4 + nb4 + nc4;
        cvt3_tf32_kernel<<<(tot + 255) / 256, 256>>>(
            (const float4*)xs,    (float4*)Xc, na4,
            (const float4*)w_in,  (float4*)Wc, nb4,
            (const float4*)c_out, (float4*)Cc, nc4);
    }

    // GEMM1: B = xs @ w_in^T  (+ fused per-chunk scan tails E)
    dim3 g1(DIM_N / 128, SEQ_L / 128);
    gemm_g1<<<g1, 128, SMEM_DYN>>>(Xc, Wc, Bp, lam, Ep, SEQ_L, DIM_N, DIM_I);

    // Scan: carries across chunks, then apply (writes tf32-rounded H)
    scan_carry<<<DIM_N / 256, 256>>>(lam, Ep, Cp);
    dim3 gs(DIM_N / 512, NCHUNK);
    scan_apply<<<gs, 256>>>(Bp, lam, Cp, Hp);

    // GEMM2 (persistent): out = H @ c_out^T + xs * d_skip
    gemm_g2<<<GRID_P, 128, SMEM_DYN>>>(Hp, Cc, out, xs, d_skip,
                                       SEQ_L, DIM_I, DIM_N);
}